// round 3
// baseline (speedup 1.0000x reference)
#include <cuda_runtime.h>
#include <math.h>

#define NT 1024
#define CD 768
#define NH 16
#define DH 48
#define HD 1536
#define CPD 128

// ---------------- scratch (device globals; no allocations allowed) ----------
__device__ __align__(16) float g_lna[NT*CD];
__device__ __align__(16) float g_sn1[NT*CD];
__device__ __align__(16) float g_sn2[NT*CD];
__device__ __align__(16) float g_tg[NT*CD];
__device__ __align__(16) float g_tk[NT*CD];
__device__ __align__(16) float g_an[NT*CD];
__device__ __align__(16) float g_q[NT*CD];
__device__ __align__(16) float g_k[NT*CD];
__device__ __align__(16) float g_v[NT*CD];
__device__ __align__(16) float g_gate[NT*CD];
__device__ __align__(16) float g_o[NT*CD];
__device__ __align__(16) float g_attout[NT*CD];
__device__ __align__(16) float g_bout[NT*CD];
__device__ __align__(16) float g_h1[NT*HD];
__device__ __align__(16) float g_h2[NT*HD];
__device__ __align__(16) float g_t3[NT*CD];
__device__ __align__(16) float g_ts[NT*CD];
__device__ __align__(16) float g_wgp[CPD*NH];
__device__ __align__(16) float g_cc[2*NH];
__device__ __align__(16) float g_bias[(size_t)NH*NT*NT];   // 64 MB [h][q][k]

__device__ __forceinline__ float sigm(float x) { return 1.f/(1.f+__expf(-x)); }

// ---------------- LayerNorm of a and s; sn1 = LN(s)*sg1, sn2 = LN(s)*sg2 ----
__global__ void ln_kernel(const float* __restrict__ a, const float* __restrict__ s,
                          const float* __restrict__ sg1, const float* __restrict__ sg2)
{
    int r = blockIdx.x, t = threadIdx.x;
    const float* ar = a + (size_t)r*CD;
    const float* sr = s + (size_t)r*CD;
    float va[3], vs[3];
    float s0=0.f,s1=0.f,s2=0.f,s3=0.f;
#pragma unroll
    for (int i=0;i<3;i++){
        va[i]=ar[t+256*i]; vs[i]=sr[t+256*i];
        s0+=va[i]; s1+=va[i]*va[i]; s2+=vs[i]; s3+=vs[i]*vs[i];
    }
    __shared__ float red[4][8];
    int lane=t&31, w=t>>5;
#pragma unroll
    for (int o=16;o;o>>=1){
        s0+=__shfl_xor_sync(0xffffffffu,s0,o);
        s1+=__shfl_xor_sync(0xffffffffu,s1,o);
        s2+=__shfl_xor_sync(0xffffffffu,s2,o);
        s3+=__shfl_xor_sync(0xffffffffu,s3,o);
    }
    if (lane==0){ red[0][w]=s0; red[1][w]=s1; red[2][w]=s2; red[3][w]=s3; }
    __syncthreads();
    float S0=0.f,S1=0.f,S2=0.f,S3=0.f;
#pragma unroll
    for (int i=0;i<8;i++){ S0+=red[0][i]; S1+=red[1][i]; S2+=red[2][i]; S3+=red[3][i]; }
    float mua=S0*(1.f/768.f), rsa=rsqrtf(S1*(1.f/768.f)-mua*mua+1e-5f);
    float mus=S2*(1.f/768.f), rss=rsqrtf(S3*(1.f/768.f)-mus*mus+1e-5f);
#pragma unroll
    for (int i=0;i<3;i++){
        int c=t+256*i; size_t idx=(size_t)r*CD+c;
        g_lna[idx]=(va[i]-mua)*rsa;
        float sv=(vs[i]-mus)*rss;
        g_sn1[idx]=sv*sg1[c];
        g_sn2[idx]=sv*sg2[c];
    }
}

// ---------------- generic SGEMM: C[M,N] = A[M,K] @ B[K,N] (+bias[N]) --------
// 64x64 tile, BK=16, 256 threads, 4x4 per thread. All dims divisible.
__global__ void __launch_bounds__(256) sgemm_kernel(
    const float* __restrict__ A, const float* __restrict__ B,
    const float* __restrict__ biasv, float* __restrict__ Cmat,
    int M, int Nn, int K)
{
    __shared__ __align__(16) float As[16][64];
    __shared__ __align__(16) float Bs[16][64];
    int tid = threadIdx.x;
    int tx = tid & 15, ty = tid >> 4;
    int row0 = blockIdx.y << 6, col0 = blockIdx.x << 6;
    int ar = tid >> 2, ac = (tid & 3) << 2;
    const float* Ag = A + (size_t)(row0 + ar)*K + ac;
    const float* Bg = B + (size_t)(tid >> 4)*Nn + col0 + ((tid & 15) << 2);
    float acc[4][4] = {};
    for (int k0 = 0; k0 < K; k0 += 16) {
        float4 av = *(const float4*)(Ag + k0);
        float4 bv = *(const float4*)(Bg + (size_t)k0*Nn);
        __syncthreads();
        As[ac+0][ar]=av.x; As[ac+1][ar]=av.y; As[ac+2][ar]=av.z; As[ac+3][ar]=av.w;
        *(float4*)&Bs[tid>>4][(tid&15)<<2] = bv;
        __syncthreads();
#pragma unroll
        for (int kk = 0; kk < 16; kk++) {
            float4 a4 = *(const float4*)&As[kk][ty<<2];
            float4 b4 = *(const float4*)&Bs[kk][tx<<2];
            acc[0][0]+=a4.x*b4.x; acc[0][1]+=a4.x*b4.y; acc[0][2]+=a4.x*b4.z; acc[0][3]+=a4.x*b4.w;
            acc[1][0]+=a4.y*b4.x; acc[1][1]+=a4.y*b4.y; acc[1][2]+=a4.y*b4.z; acc[1][3]+=a4.y*b4.w;
            acc[2][0]+=a4.z*b4.x; acc[2][1]+=a4.z*b4.y; acc[2][2]+=a4.z*b4.z; acc[2][3]+=a4.z*b4.w;
            acc[3][0]+=a4.w*b4.x; acc[3][1]+=a4.w*b4.y; acc[3][2]+=a4.w*b4.z; acc[3][3]+=a4.w*b4.w;
        }
    }
    int cbase = col0 + (tx<<2);
    float4 bb = make_float4(0.f,0.f,0.f,0.f);
    if (biasv) bb = *(const float4*)(biasv + cbase);
#pragma unroll
    for (int i=0;i<4;i++){
        int r = row0 + (ty<<2) + i;
        float4 vout;
        vout.x = acc[i][0]+bb.x; vout.y = acc[i][1]+bb.y;
        vout.z = acc[i][2]+bb.z; vout.w = acc[i][3]+bb.w;
        *(float4*)(Cmat + (size_t)r*Nn + cbase) = vout;
    }
}

// ---------------- adaLN combine: out = sigmoid(tg+bg)*lna + tk --------------
__global__ void adaln_combine_kernel(const float* __restrict__ tg,
                                     const float* __restrict__ bgv,
                                     const float* __restrict__ tk,
                                     float* __restrict__ outp)
{
    int i = blockIdx.x*256 + threadIdx.x;
    int c = i % CD;
    outp[i] = sigm(tg[i]+bgv[c])*g_lna[i] + tk[i];
}

// ---------------- pair-bias precompute: wgp = gp*wp; c1,c2 ------------------
__global__ void pair_prep_kernel(const float* __restrict__ gp,
                                 const float* __restrict__ bp,
                                 const float* __restrict__ wp)
{
    int j = threadIdx.x;  // 128
    for (int h=0; h<NH; h++) g_wgp[j*NH+h] = gp[j]*wp[j*NH+h];
    __syncthreads();
    if (j < NH) {
        float c1=0.f, c2=0.f;
        for (int jj=0; jj<CPD; jj++){ c1 += bp[jj]*wp[jj*NH+j]; c2 += g_wgp[jj*NH+j]; }
        g_cc[j]=c1; g_cc[NH+j]=c2;
    }
}

// ---------------- pair bias: bias[h,q,k] = LN(pair)@wp + beta ---------------
// one warp per pair; z[h] = rs*dot(x,wgp[:,h]) - mu*rs*c2[h] + c1[h]
__global__ void __launch_bounds__(256) pair_bias_kernel(
    const float* __restrict__ pair, const float* __restrict__ beta)
{
    __shared__ float wgp_s[CPD][NH+1];
    __shared__ float cs[2*NH];
    __shared__ float zs[8][NH];
    int t = threadIdx.x;
    for (int idx=t; idx<CPD*NH; idx+=256){ int j=idx>>4, h=idx&15; wgp_s[j][h]=g_wgp[idx]; }
    if (t < 2*NH) cs[t]=g_cc[t];
    __syncthreads();
    int w = t>>5, lane = t&31;
    int pq = blockIdx.y, pk = (blockIdx.x<<3) + w;
    const float4 x = *(const float4*)(pair + (((size_t)pq<<10)+pk)*CPD + (lane<<2));
    float sm = x.x+x.y+x.z+x.w;
    float sq = x.x*x.x + x.y*x.y + x.z*x.z + x.w*x.w;
#pragma unroll
    for (int o=16;o;o>>=1){
        sm += __shfl_xor_sync(0xffffffffu, sm, o);
        sq += __shfl_xor_sync(0xffffffffu, sq, o);
    }
    float mu = sm*(1.f/128.f);
    float rs = rsqrtf(sq*(1.f/128.f) - mu*mu + 1e-5f);
    float acc[NH];
    int j0 = lane<<2;
#pragma unroll
    for (int h=0; h<NH; h++)
        acc[h] = x.x*wgp_s[j0][h] + x.y*wgp_s[j0+1][h] + x.z*wgp_s[j0+2][h] + x.w*wgp_s[j0+3][h];
#pragma unroll
    for (int o=16;o;o>>=1){
#pragma unroll
        for (int h=0; h<NH; h++) acc[h] += __shfl_xor_sync(0xffffffffu, acc[h], o);
    }
    if (lane < NH) zs[w][lane] = rs*acc[lane] - mu*rs*cs[NH+lane] + cs[lane];
    __syncthreads();
    if (t < 128) {
        int h = t>>3, kk = t&7;
        int pkk = (blockIdx.x<<3) + kk;
        g_bias[((size_t)h<<20) + ((size_t)pq<<10) + pkk] = zs[kk][h] + beta[((size_t)pq<<10)+pkk];
    }
}

// ---------------- flash attention: o[q, h*48+d] -----------------------------
// 128 threads: 64 q-rows x 2 k-halves (split-K, merged via smem).
__global__ void __launch_bounds__(128) attn_kernel(
    const float* __restrict__ q, const float* __restrict__ k,
    const float* __restrict__ v)
{
    __shared__ __align__(16) float pool[6144];   // K [2][32][48] @0, V @3072
    __shared__ float Ms[64], Ls[64];
    int t = threadIdx.x;
    int half = t>>6, ql = t&63;
    int h = blockIdx.y;
    int qr = (blockIdx.x<<6) + ql;
    float qv[48];
#pragma unroll
    for (int d=0; d<48; d++) qv[d] = q[(size_t)qr*CD + h*48 + d]*0.14433756729740643f;
    float m = -1e30f, l = 0.f, acc[48];
#pragma unroll
    for (int d=0; d<48; d++) acc[d]=0.f;
    int kb = half<<9;
    const float* brow = g_bias + ((size_t)h<<20) + ((size_t)qr<<10) + kb;
    for (int kt=0; kt<512; kt+=32) {
        __syncthreads();
#pragma unroll
        for (int it=0; it<6; it++) {
            int i4 = t + (it<<7);            // 0..767 float4 slots
            int d4 = i4 % 12;
            int rem = i4 / 12;
            int j = rem & 31, hh = rem >> 5;
            int krow = (hh<<9) + kt + j;
            ((float4*)pool)[i4]      = *(const float4*)(k + (size_t)krow*CD + h*48 + (d4<<2));
            ((float4*)pool)[768+i4]  = *(const float4*)(v + (size_t)krow*CD + h*48 + (d4<<2));
        }
        __syncthreads();
        float bb[32];
#pragma unroll
        for (int i=0;i<8;i++){
            float4 b4 = *(const float4*)(brow + kt + (i<<2));
            bb[i*4]=b4.x; bb[i*4+1]=b4.y; bb[i*4+2]=b4.z; bb[i*4+3]=b4.w;
        }
        const float* Kt = pool + half*1536;
        const float* Vt = pool + 3072 + half*1536;
        for (int j=0; j<32; j++) {
            const float4* kr4 = (const float4*)(Kt + j*48);
            float sd = 0.f;
#pragma unroll
            for (int d4=0; d4<12; d4++){
                float4 kk4 = kr4[d4];
                sd += qv[d4*4]*kk4.x + qv[d4*4+1]*kk4.y + qv[d4*4+2]*kk4.z + qv[d4*4+3]*kk4.w;
            }
            float sc = sd + bb[j];
            if (sc > m) {
                float corr = __expf(m - sc);
                l *= corr;
#pragma unroll
                for (int d=0; d<48; d++) acc[d] *= corr;
                m = sc;
            }
            float p = __expf(sc - m);
            l += p;
            const float4* vr4 = (const float4*)(Vt + j*48);
#pragma unroll
            for (int d4=0; d4<12; d4++){
                float4 vv4 = vr4[d4];
                acc[d4*4]   += p*vv4.x; acc[d4*4+1] += p*vv4.y;
                acc[d4*4+2] += p*vv4.z; acc[d4*4+3] += p*vv4.w;
            }
        }
    }
    __syncthreads();
    if (half == 1) {
        Ms[ql]=m; Ls[ql]=l;
#pragma unroll
        for (int d=0; d<48; d++) pool[ql*48+d]=acc[d];
    }
    __syncthreads();
    if (half == 0) {
        float m2=Ms[ql], l2=Ls[ql];
        float mn=fmaxf(m,m2);
        float c1=__expf(m-mn), c2=__expf(m2-mn);
        float inv=1.f/(l*c1 + l2*c2);
#pragma unroll
        for (int d=0; d<48; d++)
            g_o[(size_t)qr*CD + h*48 + d] = (acc[d]*c1 + pool[ql*48+d]*c2)*inv;
    }
}

// ---------------- small elementwise kernels ---------------------------------
__global__ void gate_mul_kernel() {
    int i = blockIdx.x*256 + threadIdx.x;
    g_o[i] *= sigm(g_gate[i]);
}
__global__ void bout_kernel(const float* __restrict__ bso) {
    int i = blockIdx.x*256 + threadIdx.x;
    int c = i % CD;
    g_bout[i] = sigm(g_ts[i]+bso[c])*g_attout[i];
}
__global__ void swiglu_kernel() {
    int i = blockIdx.x*256 + threadIdx.x;   // < NT*HD
    float x = g_h1[i];
    g_h1[i] = x*sigm(x)*g_h2[i];
}
__global__ void final_kernel(const float* __restrict__ bs2, float* __restrict__ outp) {
    int i = blockIdx.x*256 + threadIdx.x;
    int c = i % CD;
    outp[i] = g_bout[i] + sigm(g_ts[i]+bs2[c])*g_t3[i];
}

// ---------------- launch ----------------------------------------------------
extern "C" void kernel_launch(void* const* d_in, const int* in_sizes, int n_in,
                              void* d_out, int out_size)
{
    (void)in_sizes; (void)n_in; (void)out_size;
    const float* a     = (const float*)d_in[0];
    const float* s     = (const float*)d_in[1];
    const float* pair  = (const float*)d_in[2];
    const float* beta  = (const float*)d_in[3];
    const float* sg1   = (const float*)d_in[4];
    const float* wg1   = (const float*)d_in[5];
    const float* bg1   = (const float*)d_in[6];
    const float* wsk1  = (const float*)d_in[7];
    const float* wq    = (const float*)d_in[8];
    const float* bq    = (const float*)d_in[9];
    const float* wk    = (const float*)d_in[10];
    const float* wv    = (const float*)d_in[11];
    const float* gp    = (const float*)d_in[12];
    const float* bp    = (const float*)d_in[13];
    const float* wp    = (const float*)d_in[14];
    const float* wgate = (const float*)d_in[15];
    const float* wo    = (const float*)d_in[16];
    const float* wso   = (const float*)d_in[17];
    const float* bso   = (const float*)d_in[18];
    const float* sg2   = (const float*)d_in[19];
    const float* wg2   = (const float*)d_in[20];
    const float* bg2   = (const float*)d_in[21];
    const float* wsk2  = (const float*)d_in[22];
    const float* w1    = (const float*)d_in[23];
    const float* w2    = (const float*)d_in[24];
    const float* w3    = (const float*)d_in[25];
    const float* ws2   = (const float*)d_in[26];
    const float* bs2   = (const float*)d_in[27];

    float *p_sn1,*p_sn2,*p_tg,*p_tk,*p_an,*p_q,*p_k,*p_v,*p_gate,*p_o,*p_attout,*p_ts,*p_h1,*p_h2,*p_t3;
    cudaGetSymbolAddress((void**)&p_sn1,   g_sn1);
    cudaGetSymbolAddress((void**)&p_sn2,   g_sn2);
    cudaGetSymbolAddress((void**)&p_tg,    g_tg);
    cudaGetSymbolAddress((void**)&p_tk,    g_tk);
    cudaGetSymbolAddress((void**)&p_an,    g_an);
    cudaGetSymbolAddress((void**)&p_q,     g_q);
    cudaGetSymbolAddress((void**)&p_k,     g_k);
    cudaGetSymbolAddress((void**)&p_v,     g_v);
    cudaGetSymbolAddress((void**)&p_gate,  g_gate);
    cudaGetSymbolAddress((void**)&p_o,     g_o);
    cudaGetSymbolAddress((void**)&p_attout,g_attout);
    cudaGetSymbolAddress((void**)&p_ts,    g_ts);
    cudaGetSymbolAddress((void**)&p_h1,    g_h1);
    cudaGetSymbolAddress((void**)&p_h2,    g_h2);
    cudaGetSymbolAddress((void**)&p_t3,    g_t3);

    dim3 g768(12, 16), gHID(24, 16);

    ln_kernel<<<NT, 256>>>(a, s, sg1, sg2);
    pair_prep_kernel<<<1, 128>>>(gp, bp, wp);

    // ---- AttentionPairBias ----
    sgemm_kernel<<<g768, 256>>>(p_sn1, wg1, nullptr, p_tg, NT, CD, CD);
    sgemm_kernel<<<g768, 256>>>(p_sn1, wsk1, nullptr, p_tk, NT, CD, CD);
    adaln_combine_kernel<<<NT*CD/256, 256>>>(p_tg, bg1, p_tk, p_an);
    sgemm_kernel<<<g768, 256>>>(p_an, wq, bq, p_q, NT, CD, CD);
    sgemm_kernel<<<g768, 256>>>(p_an, wk, nullptr, p_k, NT, CD, CD);
    sgemm_kernel<<<g768, 256>>>(p_an, wv, nullptr, p_v, NT, CD, CD);
    sgemm_kernel<<<g768, 256>>>(p_an, wgate, nullptr, p_gate, NT, CD, CD);
    pair_bias_kernel<<<dim3(128, 1024), 256>>>(pair, beta);
    attn_kernel<<<dim3(16, 16), 128>>>(p_q, p_k, p_v);
    gate_mul_kernel<<<NT*CD/256, 256>>>();
    sgemm_kernel<<<g768, 256>>>(p_o, wo, nullptr, p_attout, NT, CD, CD);
    sgemm_kernel<<<g768, 256>>>(s, wso, nullptr, p_ts, NT, CD, CD);
    bout_kernel<<<NT*CD/256, 256>>>(bso);

    // ---- ConditionedTransitionBlock ----
    sgemm_kernel<<<g768, 256>>>(p_sn2, wg2, nullptr, p_tg, NT, CD, CD);
    sgemm_kernel<<<g768, 256>>>(p_sn2, wsk2, nullptr, p_tk, NT, CD, CD);
    adaln_combine_kernel<<<NT*CD/256, 256>>>(p_tg, bg2, p_tk, p_an);
    sgemm_kernel<<<gHID, 256>>>(p_an, w1, nullptr, p_h1, NT, HD, CD);
    sgemm_kernel<<<gHID, 256>>>(p_an, w2, nullptr, p_h2, NT, HD, CD);
    swiglu_kernel<<<NT*HD/256, 256>>>();
    sgemm_kernel<<<g768, 256>>>(p_h1, w3, nullptr, p_t3, NT, CD, HD);
    sgemm_kernel<<<g768, 256>>>(s, ws2, nullptr, p_ts, NT, CD, CD);
    final_kernel<<<NT*CD/256, 256>>>(bs2, (float*)d_out);
}

// round 4
// speedup vs baseline: 1.4337x; 1.4337x over previous
#include <cuda_runtime.h>
#include <math.h>

#define NT 1024
#define CD 768
#define NH 16
#define DH 48
#define HD 1536
#define CPD 128

typedef unsigned long long ull;

// ---------------- f32x2 packed-math helpers (sm_100+) -----------------------
__device__ __forceinline__ ull pk2(float lo, float hi) {
    ull r; asm("mov.b64 %0, {%1, %2};" : "=l"(r) : "f"(lo), "f"(hi)); return r;
}
__device__ __forceinline__ void fma2(ull &d, ull a, ull b) {
    asm("fma.rn.f32x2 %0, %1, %2, %0;" : "+l"(d) : "l"(a), "l"(b));
}
__device__ __forceinline__ ull add2(ull a, ull b) {
    ull r; asm("add.rn.f32x2 %0, %1, %2;" : "=l"(r) : "l"(a), "l"(b)); return r;
}
__device__ __forceinline__ float2 up2(ull v) {
    float2 r; asm("mov.b64 {%0, %1}, %2;" : "=f"(r.x), "=f"(r.y) : "l"(v)); return r;
}
__device__ __forceinline__ float sigm(float x) { return 1.f/(1.f+__expf(-x)); }

// ---------------- scratch (device globals; no allocations allowed) ----------
__device__ __align__(16) float g_lna[NT*CD];
__device__ __align__(16) float g_sn1[NT*CD];
__device__ __align__(16) float g_sn2[NT*CD];
__device__ __align__(16) float g_an[NT*CD];
__device__ __align__(16) float g_o[NT*CD];
__device__ __align__(16) float g_attout[NT*CD];
__device__ __align__(16) float g_bout[NT*CD];
__device__ __align__(16) float g_h1[NT*HD];
__device__ __align__(16) float g_t3[NT*CD];
__device__ __align__(16) float g_tgk[NT*2*CD];       // tg|tk packed, stride 1536
__device__ __align__(16) float g_qkvg[NT*4*CD];      // q|k|v|gate, stride 3072
__device__ __align__(16) float g_ts2[NT*2*CD];       // s@wso | s@ws2, stride 1536
__device__ __align__(16) float g_h12[NT*2*HD];       // h1|h2, stride 3072
__device__ __align__(16) float g_pk1[CD*2*CD];       // wg1|wsk1
__device__ __align__(16) float g_pk2[CD*2*CD];       // wg2|wsk2
__device__ __align__(16) float g_wqkvg[CD*4*CD];     // wq|wk|wv|wgate
__device__ __align__(16) float g_wss[CD*2*CD];       // wso|ws2
__device__ __align__(16) float g_w12[CD*2*HD];       // w1|w2
__device__ __align__(16) float g_bqkv[4*CD];
__device__ __align__(16) float g_wgp[CPD*NH];
__device__ __align__(16) float g_cc[2*NH];
__device__ __align__(16) float g_bias[(size_t)NH*NT*NT];   // 64 MB [h][q][k]

// ---------------- LayerNorm of a and s; sn1 = LN(s)*sg1, sn2 = LN(s)*sg2 ----
__global__ void ln_kernel(const float* __restrict__ a, const float* __restrict__ s,
                          const float* __restrict__ sg1, const float* __restrict__ sg2)
{
    int r = blockIdx.x, t = threadIdx.x;
    const float* ar = a + (size_t)r*CD;
    const float* sr = s + (size_t)r*CD;
    float va[3], vs[3];
    float s0=0.f,s1=0.f,s2=0.f,s3=0.f;
#pragma unroll
    for (int i=0;i<3;i++){
        va[i]=ar[t+256*i]; vs[i]=sr[t+256*i];
        s0+=va[i]; s1+=va[i]*va[i]; s2+=vs[i]; s3+=vs[i]*vs[i];
    }
    __shared__ float red[4][8];
    int lane=t&31, w=t>>5;
#pragma unroll
    for (int o=16;o;o>>=1){
        s0+=__shfl_xor_sync(0xffffffffu,s0,o);
        s1+=__shfl_xor_sync(0xffffffffu,s1,o);
        s2+=__shfl_xor_sync(0xffffffffu,s2,o);
        s3+=__shfl_xor_sync(0xffffffffu,s3,o);
    }
    if (lane==0){ red[0][w]=s0; red[1][w]=s1; red[2][w]=s2; red[3][w]=s3; }
    __syncthreads();
    float S0=0.f,S1=0.f,S2=0.f,S3=0.f;
#pragma unroll
    for (int i=0;i<8;i++){ S0+=red[0][i]; S1+=red[1][i]; S2+=red[2][i]; S3+=red[3][i]; }
    float mua=S0*(1.f/768.f), rsa=rsqrtf(S1*(1.f/768.f)-mua*mua+1e-5f);
    float mus=S2*(1.f/768.f), rss=rsqrtf(S3*(1.f/768.f)-mus*mus+1e-5f);
#pragma unroll
    for (int i=0;i<3;i++){
        int c=t+256*i; size_t idx=(size_t)r*CD+c;
        g_lna[idx]=(va[i]-mua)*rsa;
        float sv=(vs[i]-mus)*rss;
        g_sn1[idx]=sv*sg1[c];
        g_sn2[idx]=sv*sg2[c];
    }
}

// ---------------- weight packing: dst[r, colofs+c] = src[r, c], 768 rows ----
__global__ void pack_kernel(const float* __restrict__ src, float* __restrict__ dst,
                            int W4, int Wtot, int colofs)
{
    int i = blockIdx.x*256 + threadIdx.x;
    int r = i / W4, c4 = i - r*W4;
    *(float4*)(dst + (size_t)r*Wtot + colofs + (c4<<2)) =
        *(const float4*)(src + (size_t)r*(W4<<2) + (c4<<2));
}
__global__ void bfill_kernel(const float* __restrict__ bq)
{
    int i = blockIdx.x*256 + threadIdx.x;
    g_bqkv[i] = (i < CD) ? bq[i] : 0.f;
}

// ---------------- SGEMM: 64x64 tile, 64 threads, 8x8/thread, f32x2 ----------
__global__ void __launch_bounds__(64) sgemm64_kernel(
    const float* __restrict__ A, const float* __restrict__ B,
    const float* __restrict__ biasv, float* __restrict__ C,
    int Nn, int K)
{
    __shared__ __align__(16) float As[2][8][64];
    __shared__ __align__(16) float Bs[2][8][64];
    int t = threadIdx.x;
    int tx = t & 7, ty = t >> 3;
    int row0 = blockIdx.y << 6, col0 = blockIdx.x << 6;
    const float* Ag = A + (size_t)(row0 + t)*K;
    const float* Bg = B + (size_t)(t>>3)*Nn + col0 + ((t&7)<<2);

    ull acc[8][4];
#pragma unroll
    for (int i=0;i<8;i++)
#pragma unroll
        for (int j=0;j<4;j++) acc[i][j]=0ull;

    int nt = K >> 3;
    float4 a0 = *(const float4*)(Ag);
    float4 a1 = *(const float4*)(Ag + 4);
    float4 b0 = *(const float4*)(Bg);
    float4 b1 = *(const float4*)(Bg + 32);
    {
        As[0][0][t]=a0.x; As[0][1][t]=a0.y; As[0][2][t]=a0.z; As[0][3][t]=a0.w;
        As[0][4][t]=a1.x; As[0][5][t]=a1.y; As[0][6][t]=a1.z; As[0][7][t]=a1.w;
        *(float4*)&Bs[0][t>>3][(t&7)<<2] = b0;
        *(float4*)&Bs[0][t>>3][((t&7)<<2)+32] = b1;
    }
    __syncthreads();

    for (int kt = 0; kt < nt; kt++) {
        int cur = kt & 1;
        bool more = (kt+1) < nt;
        if (more) {
            a0 = *(const float4*)(Ag + (kt+1)*8);
            a1 = *(const float4*)(Ag + (kt+1)*8 + 4);
            b0 = *(const float4*)(Bg + (size_t)(kt+1)*8*Nn);
            b1 = *(const float4*)(Bg + (size_t)(kt+1)*8*Nn + 32);
        }
#pragma unroll
        for (int kk = 0; kk < 8; kk++) {
            float4 av0 = *(const float4*)&As[cur][kk][ty<<3];
            float4 av1 = *(const float4*)&As[cur][kk][(ty<<3)+4];
            float4 bv0 = *(const float4*)&Bs[cur][kk][tx<<3];
            float4 bv1 = *(const float4*)&Bs[cur][kk][(tx<<3)+4];
            ull bp0 = pk2(bv0.x,bv0.y), bp1 = pk2(bv0.z,bv0.w);
            ull bp2 = pk2(bv1.x,bv1.y), bp3 = pk2(bv1.z,bv1.w);
            float aarr[8] = {av0.x,av0.y,av0.z,av0.w,av1.x,av1.y,av1.z,av1.w};
#pragma unroll
            for (int i=0;i<8;i++){
                ull aa = pk2(aarr[i], aarr[i]);
                fma2(acc[i][0], aa, bp0);
                fma2(acc[i][1], aa, bp1);
                fma2(acc[i][2], aa, bp2);
                fma2(acc[i][3], aa, bp3);
            }
        }
        if (more) {
            int nx = cur ^ 1;
            As[nx][0][t]=a0.x; As[nx][1][t]=a0.y; As[nx][2][t]=a0.z; As[nx][3][t]=a0.w;
            As[nx][4][t]=a1.x; As[nx][5][t]=a1.y; As[nx][6][t]=a1.z; As[nx][7][t]=a1.w;
            *(float4*)&Bs[nx][t>>3][(t&7)<<2] = b0;
            *(float4*)&Bs[nx][t>>3][((t&7)<<2)+32] = b1;
            __syncthreads();
        }
    }

    int col = col0 + (tx<<3);
    float4 bb0 = make_float4(0.f,0.f,0.f,0.f), bb1 = bb0;
    if (biasv) { bb0 = *(const float4*)(biasv + col); bb1 = *(const float4*)(biasv + col + 4); }
#pragma unroll
    for (int i=0;i<8;i++){
        int r = row0 + (ty<<3) + i;
        float2 p0=up2(acc[i][0]), p1=up2(acc[i][1]), p2=up2(acc[i][2]), p3=up2(acc[i][3]);
        float4 o0 = make_float4(p0.x+bb0.x, p0.y+bb0.y, p1.x+bb0.z, p1.y+bb0.w);
        float4 o1 = make_float4(p2.x+bb1.x, p2.y+bb1.y, p3.x+bb1.z, p3.y+bb1.w);
        *(float4*)(C + (size_t)r*Nn + col) = o0;
        *(float4*)(C + (size_t)r*Nn + col + 4) = o1;
    }
}

// ---------------- adaLN combine: an = sigmoid(tg+bg)*lna + tk ---------------
__global__ void adaln_combine_kernel(const float* __restrict__ tgk,
                                     const float* __restrict__ bgv,
                                     float* __restrict__ outp)
{
    int i = blockIdx.x*256 + threadIdx.x;
    int r = i / CD, c = i - r*CD;
    float tg = tgk[(size_t)r*1536 + c];
    float tk = tgk[(size_t)r*1536 + 768 + c];
    outp[i] = sigm(tg + bgv[c])*g_lna[i] + tk;
}

// ---------------- pair-bias precompute: wgp = gp*wp; c1,c2 ------------------
__global__ void pair_prep_kernel(const float* __restrict__ gp,
                                 const float* __restrict__ bp,
                                 const float* __restrict__ wp)
{
    int j = threadIdx.x;  // 128
    for (int h=0; h<NH; h++) g_wgp[j*NH+h] = gp[j]*wp[j*NH+h];
    __syncthreads();
    if (j < NH) {
        float c1=0.f, c2=0.f;
        for (int jj=0; jj<CPD; jj++){ c1 += bp[jj]*wp[jj*NH+j]; c2 += g_wgp[jj*NH+j]; }
        g_cc[j]=c1; g_cc[NH+j]=c2;
    }
}

// ---------------- pair bias: bias[h,q,k] = LN(pair)@wgp(+consts) + beta -----
// Block: 64 pairs staged in smem; 4-thread team per pair; f32x2 accumulation.
__global__ void __launch_bounds__(256) pair_bias_kernel(
    const float* __restrict__ pair, const float* __restrict__ beta)
{
    __shared__ __align__(16) float xs[64][132];   // padded rows (528B, 16B-aligned)
    __shared__ __align__(16) float wsf[128*20];   // wgp rows padded to 20 floats
    __shared__ float csm[2*NH];
    int t = threadIdx.x;
    int q = blockIdx.y, k0 = blockIdx.x << 6;

    // stage wgp + consts
    for (int i=t; i<CPD*NH; i+=256) wsf[(i>>4)*20 + (i&15)] = g_wgp[i];
    if (t < 2*NH) csm[t] = g_cc[t];
    // stage 64 pair rows, coalesced float4
#pragma unroll
    for (int it=0; it<8; it++) {
        int i = t + (it<<8);
        int row = i >> 5, c4 = i & 31;
        *(float4*)&xs[row][c4<<2] =
            *(const float4*)(pair + (((size_t)((q<<10) + k0 + row))<<7) + (c4<<2));
    }
    __syncthreads();

    int p = t >> 2, c = t & 3;
    float sm = 0.f, sq = 0.f;
    ull acc2[8];
#pragma unroll
    for (int m=0;m<8;m++) acc2[m]=0ull;

    const float* xrow = &xs[p][0];
#pragma unroll
    for (int i=0;i<32;i++){
        int j = c + (i<<2);
        float xv = xrow[j];
        sm += xv; sq = fmaf(xv, xv, sq);
        ull xx = pk2(xv, xv);
        const float* wr = wsf + j*20;
        float4 w0 = *(const float4*)(wr);
        float4 w1 = *(const float4*)(wr+4);
        float4 w2 = *(const float4*)(wr+8);
        float4 w3 = *(const float4*)(wr+12);
        fma2(acc2[0], xx, pk2(w0.x,w0.y)); fma2(acc2[1], xx, pk2(w0.z,w0.w));
        fma2(acc2[2], xx, pk2(w1.x,w1.y)); fma2(acc2[3], xx, pk2(w1.z,w1.w));
        fma2(acc2[4], xx, pk2(w2.x,w2.y)); fma2(acc2[5], xx, pk2(w2.z,w2.w));
        fma2(acc2[6], xx, pk2(w3.x,w3.y)); fma2(acc2[7], xx, pk2(w3.z,w3.w));
    }
    // team reduce (lanes xor 1, 2)
#pragma unroll
    for (int o=1;o<4;o<<=1){
        sm += __shfl_xor_sync(0xffffffffu, sm, o);
        sq += __shfl_xor_sync(0xffffffffu, sq, o);
#pragma unroll
        for (int m=0;m<8;m++){
            ull v = __shfl_xor_sync(0xffffffffu, acc2[m], o);
            acc2[m] = add2(acc2[m], v);
        }
    }
    if (c == 0) {
        float mu = sm*(1.f/128.f);
        float rs = rsqrtf(sq*(1.f/128.f) - mu*mu + 1e-5f);
        int kk = k0 + p;
        float bv = beta[((size_t)q<<10) + kk];
        float murs = mu*rs;
#pragma unroll
        for (int m=0;m<8;m++){
            float2 v = up2(acc2[m]);
            int h0 = m<<1;
            float z0 = rs*v.x - murs*csm[NH+h0]   + csm[h0]   + bv;
            float z1 = rs*v.y - murs*csm[NH+h0+1] + csm[h0+1] + bv;
            g_bias[((size_t)h0<<20)     + ((size_t)q<<10) + kk] = z0;
            g_bias[((size_t)(h0+1)<<20) + ((size_t)q<<10) + kk] = z1;
        }
    }
}

// ---------------- flash attention: o[q, h*48+d] -----------------------------
// q/k/v come from packed qkvg buffer with row stride 3072.
__global__ void __launch_bounds__(128) attn_kernel(
    const float* __restrict__ qp, const float* __restrict__ kp,
    const float* __restrict__ vp)
{
    __shared__ __align__(16) float pool[6144];
    __shared__ float Ms[64], Ls[64];
    int t = threadIdx.x;
    int half = t>>6, ql = t&63;
    int h = blockIdx.y;
    int qr = (blockIdx.x<<6) + ql;
    float qv[48];
#pragma unroll
    for (int d=0; d<48; d++) qv[d] = qp[(size_t)qr*3072 + h*48 + d]*0.14433756729740643f;
    float m = -1e30f, l = 0.f, acc[48];
#pragma unroll
    for (int d=0; d<48; d++) acc[d]=0.f;
    int kb = half<<9;
    const float* brow = g_bias + ((size_t)h<<20) + ((size_t)qr<<10) + kb;
    for (int kt=0; kt<512; kt+=32) {
        __syncthreads();
#pragma unroll
        for (int it=0; it<6; it++) {
            int i4 = t + (it<<7);
            int d4 = i4 % 12;
            int rem = i4 / 12;
            int j = rem & 31, hh = rem >> 5;
            int krow = (hh<<9) + kt + j;
            ((float4*)pool)[i4]      = *(const float4*)(kp + (size_t)krow*3072 + h*48 + (d4<<2));
            ((float4*)pool)[768+i4]  = *(const float4*)(vp + (size_t)krow*3072 + h*48 + (d4<<2));
        }
        __syncthreads();
        float bb[32];
#pragma unroll
        for (int i=0;i<8;i++){
            float4 b4 = *(const float4*)(brow + kt + (i<<2));
            bb[i*4]=b4.x; bb[i*4+1]=b4.y; bb[i*4+2]=b4.z; bb[i*4+3]=b4.w;
        }
        const float* Kt = pool + half*1536;
        const float* Vt = pool + 3072 + half*1536;
        for (int j=0; j<32; j++) {
            const float4* kr4 = (const float4*)(Kt + j*48);
            float sd = 0.f;
#pragma unroll
            for (int d4=0; d4<12; d4++){
                float4 kk4 = kr4[d4];
                sd += qv[d4*4]*kk4.x + qv[d4*4+1]*kk4.y + qv[d4*4+2]*kk4.z + qv[d4*4+3]*kk4.w;
            }
            float sc = sd + bb[j];
            if (sc > m) {
                float corr = __expf(m - sc);
                l *= corr;
#pragma unroll
                for (int d=0; d<48; d++) acc[d] *= corr;
                m = sc;
            }
            float pw = __expf(sc - m);
            l += pw;
            const float4* vr4 = (const float4*)(Vt + j*48);
#pragma unroll
            for (int d4=0; d4<12; d4++){
                float4 vv4 = vr4[d4];
                acc[d4*4]   += pw*vv4.x; acc[d4*4+1] += pw*vv4.y;
                acc[d4*4+2] += pw*vv4.z; acc[d4*4+3] += pw*vv4.w;
            }
        }
    }
    __syncthreads();
    if (half == 1) {
        Ms[ql]=m; Ls[ql]=l;
#pragma unroll
        for (int d=0; d<48; d++) pool[ql*48+d]=acc[d];
    }
    __syncthreads();
    if (half == 0) {
        float m2=Ms[ql], l2=Ls[ql];
        float mn=fmaxf(m,m2);
        float c1=__expf(m-mn), c2=__expf(m2-mn);
        float inv=1.f/(l*c1 + l2*c2);
#pragma unroll
        for (int d=0; d<48; d++)
            g_o[(size_t)qr*CD + h*48 + d] = (acc[d]*c1 + pool[ql*48+d]*c2)*inv;
    }
}

// ---------------- small elementwise kernels ---------------------------------
__global__ void gate_mul_kernel() {
    int i = blockIdx.x*256 + threadIdx.x;
    int r = i / CD, c = i - r*CD;
    g_o[i] *= sigm(g_qkvg[(size_t)r*3072 + 2304 + c]);
}
__global__ void bout_kernel(const float* __restrict__ bso) {
    int i = blockIdx.x*256 + threadIdx.x;
    int r = i / CD, c = i - r*CD;
    g_bout[i] = sigm(g_ts2[(size_t)r*1536 + c] + bso[c])*g_attout[i];
}
__global__ void swiglu_kernel() {
    int i = blockIdx.x*256 + threadIdx.x;   // < NT*HD
    int r = i / HD, c = i - r*HD;
    float x = g_h12[(size_t)r*3072 + c];
    float y = g_h12[(size_t)r*3072 + 1536 + c];
    g_h1[i] = x*sigm(x)*y;
}
__global__ void final_kernel(const float* __restrict__ bs2, float* __restrict__ outp) {
    int i = blockIdx.x*256 + threadIdx.x;
    int r = i / CD, c = i - r*CD;
    outp[i] = g_bout[i] + sigm(g_ts2[(size_t)r*1536 + 768 + c] + bs2[c])*g_t3[i];
}

// ---------------- launch ----------------------------------------------------
extern "C" void kernel_launch(void* const* d_in, const int* in_sizes, int n_in,
                              void* d_out, int out_size)
{
    (void)in_sizes; (void)n_in; (void)out_size;
    const float* a     = (const float*)d_in[0];
    const float* s     = (const float*)d_in[1];
    const float* pair  = (const float*)d_in[2];
    const float* beta  = (const float*)d_in[3];
    const float* sg1   = (const float*)d_in[4];
    const float* wg1   = (const float*)d_in[5];
    const float* bg1   = (const float*)d_in[6];
    const float* wsk1  = (const float*)d_in[7];
    const float* wq    = (const float*)d_in[8];
    const float* bq    = (const float*)d_in[9];
    const float* wk    = (const float*)d_in[10];
    const float* wv    = (const float*)d_in[11];
    const float* gp    = (const float*)d_in[12];
    const float* bp    = (const float*)d_in[13];
    const float* wp    = (const float*)d_in[14];
    const float* wgate = (const float*)d_in[15];
    const float* wo    = (const float*)d_in[16];
    const float* wso   = (const float*)d_in[17];
    const float* bso   = (const float*)d_in[18];
    const float* sg2   = (const float*)d_in[19];
    const float* wg2   = (const float*)d_in[20];
    const float* bg2   = (const float*)d_in[21];
    const float* wsk2  = (const float*)d_in[22];
    const float* w1    = (const float*)d_in[23];
    const float* w2    = (const float*)d_in[24];
    const float* w3    = (const float*)d_in[25];
    const float* ws2   = (const float*)d_in[26];
    const float* bs2   = (const float*)d_in[27];

    float *p_sn1,*p_sn2,*p_an,*p_o,*p_attout,*p_h1,*p_t3,*p_tgk,*p_qkvg,*p_ts2,*p_h12;
    float *p_pk1,*p_pk2,*p_wqkvg,*p_wss,*p_w12,*p_bqkv;
    cudaGetSymbolAddress((void**)&p_sn1,   g_sn1);
    cudaGetSymbolAddress((void**)&p_sn2,   g_sn2);
    cudaGetSymbolAddress((void**)&p_an,    g_an);
    cudaGetSymbolAddress((void**)&p_o,     g_o);
    cudaGetSymbolAddress((void**)&p_attout,g_attout);
    cudaGetSymbolAddress((void**)&p_h1,    g_h1);
    cudaGetSymbolAddress((void**)&p_t3,    g_t3);
    cudaGetSymbolAddress((void**)&p_tgk,   g_tgk);
    cudaGetSymbolAddress((void**)&p_qkvg,  g_qkvg);
    cudaGetSymbolAddress((void**)&p_ts2,   g_ts2);
    cudaGetSymbolAddress((void**)&p_h12,   g_h12);
    cudaGetSymbolAddress((void**)&p_pk1,   g_pk1);
    cudaGetSymbolAddress((void**)&p_pk2,   g_pk2);
    cudaGetSymbolAddress((void**)&p_wqkvg, g_wqkvg);
    cudaGetSymbolAddress((void**)&p_wss,   g_wss);
    cudaGetSymbolAddress((void**)&p_w12,   g_w12);
    cudaGetSymbolAddress((void**)&p_bqkv,  g_bqkv);

    // ---- prep: LN, pair constants, weight packing ----
    ln_kernel<<<NT, 256>>>(a, s, sg1, sg2);
    pair_prep_kernel<<<1, 128>>>(gp, bp, wp);
    pack_kernel<<<576, 256>>>(wg1,   p_pk1,   192, 1536, 0);
    pack_kernel<<<576, 256>>>(wsk1,  p_pk1,   192, 1536, 768);
    pack_kernel<<<576, 256>>>(wq,    p_wqkvg, 192, 3072, 0);
    pack_kernel<<<576, 256>>>(wk,    p_wqkvg, 192, 3072, 768);
    pack_kernel<<<576, 256>>>(wv,    p_wqkvg, 192, 3072, 1536);
    pack_kernel<<<576, 256>>>(wgate, p_wqkvg, 192, 3072, 2304);
    pack_kernel<<<576, 256>>>(wso,   p_wss,   192, 1536, 0);
    pack_kernel<<<576, 256>>>(ws2,   p_wss,   192, 1536, 768);
    pack_kernel<<<576, 256>>>(wg2,   p_pk2,   192, 1536, 0);
    pack_kernel<<<576, 256>>>(wsk2,  p_pk2,   192, 1536, 768);
    pack_kernel<<<1152,256>>>(w1,    p_w12,   384, 3072, 0);
    pack_kernel<<<1152,256>>>(w2,    p_w12,   384, 3072, 1536);
    bfill_kernel<<<12, 256>>>(bq);

    // ---- pair bias (independent long pole, kick off early) ----
    pair_bias_kernel<<<dim3(16, 1024), 256>>>(pair, beta);

    // ---- AttentionPairBias ----
    sgemm64_kernel<<<dim3(24,16), 64>>>(p_sn1, p_pk1, nullptr, p_tgk, 1536, 768);
    adaln_combine_kernel<<<NT*CD/256, 256>>>(p_tgk, bg1, p_an);
    sgemm64_kernel<<<dim3(48,16), 64>>>(p_an, p_wqkvg, p_bqkv, p_qkvg, 3072, 768);
    attn_kernel<<<dim3(16, 16), 128>>>(p_qkvg, p_qkvg + 768, p_qkvg + 1536);
    gate_mul_kernel<<<NT*CD/256, 256>>>();
    sgemm64_kernel<<<dim3(12,16), 64>>>(p_o, wo, nullptr, p_attout, 768, 768);
    sgemm64_kernel<<<dim3(24,16), 64>>>(s, p_wss, nullptr, p_ts2, 1536, 768);
    bout_kernel<<<NT*CD/256, 256>>>(bso);

    // ---- ConditionedTransitionBlock ----
    sgemm64_kernel<<<dim3(24,16), 64>>>(p_sn2, p_pk2, nullptr, p_tgk, 1536, 768);
    adaln_combine_kernel<<<NT*CD/256, 256>>>(p_tgk, bg2, p_an);
    sgemm64_kernel<<<dim3(48,16), 64>>>(p_an, p_w12, nullptr, p_h12, 3072, 768);
    swiglu_kernel<<<NT*HD/256, 256>>>();
    sgemm64_kernel<<<dim3(12,16), 64>>>(p_h1, w3, nullptr, p_t3, 768, 1536);
    final_kernel<<<NT*CD/256, 256>>>(bs2, (float*)d_out);
}

// round 5
// speedup vs baseline: 1.4375x; 1.0026x over previous
#include <cuda_runtime.h>
#include <math.h>

#define NT 1024
#define CD 768
#define NH 16
#define DH 48
#define HD 1536
#define CPD 128

typedef unsigned long long ull;

// ---------------- f32x2 packed-math helpers (sm_100+) -----------------------
__device__ __forceinline__ ull pk2(float lo, float hi) {
    ull r; asm("mov.b64 %0, {%1, %2};" : "=l"(r) : "f"(lo), "f"(hi)); return r;
}
__device__ __forceinline__ void fma2(ull &d, ull a, ull b) {
    asm("fma.rn.f32x2 %0, %1, %2, %0;" : "+l"(d) : "l"(a), "l"(b));
}
__device__ __forceinline__ ull add2(ull a, ull b) {
    ull r; asm("add.rn.f32x2 %0, %1, %2;" : "=l"(r) : "l"(a), "l"(b)); return r;
}
__device__ __forceinline__ float2 up2(ull v) {
    float2 r; asm("mov.b64 {%0, %1}, %2;" : "=f"(r.x), "=f"(r.y) : "l"(v)); return r;
}
__device__ __forceinline__ float sigm(float x) { return 1.f/(1.f+__expf(-x)); }

// ---------------- scratch (device globals; no allocations allowed) ----------
__device__ __align__(16) float g_lna[NT*CD];
__device__ __align__(16) float g_sn1[NT*CD];
__device__ __align__(16) float g_sn2[NT*CD];
__device__ __align__(16) float g_an[NT*CD];
__device__ __align__(16) float g_o[NT*CD];
__device__ __align__(16) float g_attout[NT*CD];
__device__ __align__(16) float g_bout[NT*CD];
__device__ __align__(16) float g_h1[NT*HD];
__device__ __align__(16) float g_t3[NT*CD];
__device__ __align__(16) float g_tgk[NT*2*CD];       // tg|tk packed, stride 1536
__device__ __align__(16) float g_qkvg[NT*4*CD];      // q|k|v|gate, stride 3072
__device__ __align__(16) float g_ts2[NT*2*CD];       // s@wso | s@ws2, stride 1536
__device__ __align__(16) float g_h12[NT*2*HD];       // h1|h2, stride 3072
__device__ __align__(16) float g_pk1[CD*2*CD];       // wg1|wsk1
__device__ __align__(16) float g_pk2[CD*2*CD];       // wg2|wsk2
__device__ __align__(16) float g_wqkvg[CD*4*CD];     // wq|wk|wv|wgate
__device__ __align__(16) float g_wss[CD*2*CD];       // wso|ws2
__device__ __align__(16) float g_w12[CD*2*HD];       // w1|w2
__device__ __align__(16) float g_bqkv[4*CD];
__device__ __align__(16) float g_wgp[CPD*NH];
__device__ __align__(16) float g_cc[2*NH];
__device__ __align__(16) float g_bias[(size_t)NH*NT*NT];   // 64 MB [h][q][k]

// ---------------- LayerNorm of a and s; sn1 = LN(s)*sg1, sn2 = LN(s)*sg2 ----
__global__ void ln_kernel(const float* __restrict__ a, const float* __restrict__ s,
                          const float* __restrict__ sg1, const float* __restrict__ sg2)
{
    int r = blockIdx.x, t = threadIdx.x;
    const float* ar = a + (size_t)r*CD;
    const float* sr = s + (size_t)r*CD;
    float va[3], vs[3];
    float s0=0.f,s1=0.f,s2=0.f,s3=0.f;
#pragma unroll
    for (int i=0;i<3;i++){
        va[i]=ar[t+256*i]; vs[i]=sr[t+256*i];
        s0+=va[i]; s1+=va[i]*va[i]; s2+=vs[i]; s3+=vs[i]*vs[i];
    }
    __shared__ float red[4][8];
    int lane=t&31, w=t>>5;
#pragma unroll
    for (int o=16;o;o>>=1){
        s0+=__shfl_xor_sync(0xffffffffu,s0,o);
        s1+=__shfl_xor_sync(0xffffffffu,s1,o);
        s2+=__shfl_xor_sync(0xffffffffu,s2,o);
        s3+=__shfl_xor_sync(0xffffffffu,s3,o);
    }
    if (lane==0){ red[0][w]=s0; red[1][w]=s1; red[2][w]=s2; red[3][w]=s3; }
    __syncthreads();
    float S0=0.f,S1=0.f,S2=0.f,S3=0.f;
#pragma unroll
    for (int i=0;i<8;i++){ S0+=red[0][i]; S1+=red[1][i]; S2+=red[2][i]; S3+=red[3][i]; }
    float mua=S0*(1.f/768.f), rsa=rsqrtf(S1*(1.f/768.f)-mua*mua+1e-5f);
    float mus=S2*(1.f/768.f), rss=rsqrtf(S3*(1.f/768.f)-mus*mus+1e-5f);
#pragma unroll
    for (int i=0;i<3;i++){
        int c=t+256*i; size_t idx=(size_t)r*CD+c;
        g_lna[idx]=(va[i]-mua)*rsa;
        float sv=(vs[i]-mus)*rss;
        g_sn1[idx]=sv*sg1[c];
        g_sn2[idx]=sv*sg2[c];
    }
}

// ---------------- weight packing: dst[r, colofs+c] = src[r, c], 768 rows ----
__global__ void pack_kernel(const float* __restrict__ src, float* __restrict__ dst,
                            int W4, int Wtot, int colofs)
{
    int i = blockIdx.x*256 + threadIdx.x;
    int r = i / W4, c4 = i - r*W4;
    *(float4*)(dst + (size_t)r*Wtot + colofs + (c4<<2)) =
        *(const float4*)(src + (size_t)r*(W4<<2) + (c4<<2));
}
__global__ void bfill_kernel(const float* __restrict__ bq)
{
    int i = blockIdx.x*256 + threadIdx.x;
    g_bqkv[i] = (i < CD) ? bq[i] : 0.f;
}

// ---------------- SGEMM: 64x64 tile, 64 threads, 8x8/thread, f32x2 ----------
__global__ void __launch_bounds__(64) sgemm64_kernel(
    const float* __restrict__ A, const float* __restrict__ B,
    const float* __restrict__ biasv, float* __restrict__ C,
    int Nn, int K)
{
    __shared__ __align__(16) float As[2][8][64];
    __shared__ __align__(16) float Bs[2][8][64];
    int t = threadIdx.x;
    int tx = t & 7, ty = t >> 3;
    int row0 = blockIdx.y << 6, col0 = blockIdx.x << 6;
    const float* Ag = A + (size_t)(row0 + t)*K;
    const float* Bg = B + (size_t)(t>>3)*Nn + col0 + ((t&7)<<2);

    ull acc[8][4];
#pragma unroll
    for (int i=0;i<8;i++)
#pragma unroll
        for (int j=0;j<4;j++) acc[i][j]=0ull;

    int nt = K >> 3;
    float4 a0 = *(const float4*)(Ag);
    float4 a1 = *(const float4*)(Ag + 4);
    float4 b0 = *(const float4*)(Bg);
    float4 b1 = *(const float4*)(Bg + 32);
    {
        As[0][0][t]=a0.x; As[0][1][t]=a0.y; As[0][2][t]=a0.z; As[0][3][t]=a0.w;
        As[0][4][t]=a1.x; As[0][5][t]=a1.y; As[0][6][t]=a1.z; As[0][7][t]=a1.w;
        *(float4*)&Bs[0][t>>3][(t&7)<<2] = b0;
        *(float4*)&Bs[0][t>>3][((t&7)<<2)+32] = b1;
    }
    __syncthreads();

    for (int kt = 0; kt < nt; kt++) {
        int cur = kt & 1;
        bool more = (kt+1) < nt;
        if (more) {
            a0 = *(const float4*)(Ag + (kt+1)*8);
            a1 = *(const float4*)(Ag + (kt+1)*8 + 4);
            b0 = *(const float4*)(Bg + (size_t)(kt+1)*8*Nn);
            b1 = *(const float4*)(Bg + (size_t)(kt+1)*8*Nn + 32);
        }
#pragma unroll
        for (int kk = 0; kk < 8; kk++) {
            float4 av0 = *(const float4*)&As[cur][kk][ty<<3];
            float4 av1 = *(const float4*)&As[cur][kk][(ty<<3)+4];
            float4 bv0 = *(const float4*)&Bs[cur][kk][tx<<3];
            float4 bv1 = *(const float4*)&Bs[cur][kk][(tx<<3)+4];
            ull bp0 = pk2(bv0.x,bv0.y), bp1 = pk2(bv0.z,bv0.w);
            ull bp2 = pk2(bv1.x,bv1.y), bp3 = pk2(bv1.z,bv1.w);
            float aarr[8] = {av0.x,av0.y,av0.z,av0.w,av1.x,av1.y,av1.z,av1.w};
#pragma unroll
            for (int i=0;i<8;i++){
                ull aa = pk2(aarr[i], aarr[i]);
                fma2(acc[i][0], aa, bp0);
                fma2(acc[i][1], aa, bp1);
                fma2(acc[i][2], aa, bp2);
                fma2(acc[i][3], aa, bp3);
            }
        }
        if (more) {
            int nx = cur ^ 1;
            As[nx][0][t]=a0.x; As[nx][1][t]=a0.y; As[nx][2][t]=a0.z; As[nx][3][t]=a0.w;
            As[nx][4][t]=a1.x; As[nx][5][t]=a1.y; As[nx][6][t]=a1.z; As[nx][7][t]=a1.w;
            *(float4*)&Bs[nx][t>>3][(t&7)<<2] = b0;
            *(float4*)&Bs[nx][t>>3][((t&7)<<2)+32] = b1;
            __syncthreads();
        }
    }

    int col = col0 + (tx<<3);
    float4 bb0 = make_float4(0.f,0.f,0.f,0.f), bb1 = bb0;
    if (biasv) { bb0 = *(const float4*)(biasv + col); bb1 = *(const float4*)(biasv + col + 4); }
#pragma unroll
    for (int i=0;i<8;i++){
        int r = row0 + (ty<<3) + i;
        float2 p0=up2(acc[i][0]), p1=up2(acc[i][1]), p2=up2(acc[i][2]), p3=up2(acc[i][3]);
        float4 o0 = make_float4(p0.x+bb0.x, p0.y+bb0.y, p1.x+bb0.z, p1.y+bb0.w);
        float4 o1 = make_float4(p2.x+bb1.x, p2.y+bb1.y, p3.x+bb1.z, p3.y+bb1.w);
        *(float4*)(C + (size_t)r*Nn + col) = o0;
        *(float4*)(C + (size_t)r*Nn + col + 4) = o1;
    }
}

// ---------------- adaLN combine: an = sigmoid(tg+bg)*lna + tk ---------------
__global__ void adaln_combine_kernel(const float* __restrict__ tgk,
                                     const float* __restrict__ bgv,
                                     float* __restrict__ outp)
{
    int i = blockIdx.x*256 + threadIdx.x;
    int r = i / CD, c = i - r*CD;
    float tg = tgk[(size_t)r*1536 + c];
    float tk = tgk[(size_t)r*1536 + 768 + c];
    outp[i] = sigm(tg + bgv[c])*g_lna[i] + tk;
}

// ---------------- pair-bias precompute: wgp = gp*wp; c1,c2 ------------------
__global__ void pair_prep_kernel(const float* __restrict__ gp,
                                 const float* __restrict__ bp,
                                 const float* __restrict__ wp)
{
    int j = threadIdx.x;  // 128
    for (int h=0; h<NH; h++) g_wgp[j*NH+h] = gp[j]*wp[j*NH+h];
    __syncthreads();
    if (j < NH) {
        float c1=0.f, c2=0.f;
        for (int jj=0; jj<CPD; jj++){ c1 += bp[jj]*wp[jj*NH+j]; c2 += g_wgp[jj*NH+j]; }
        g_cc[j]=c1; g_cc[NH+j]=c2;
    }
}

// ---------------- pair bias: bias[h,q,k] = LN(pair)@wgp(+consts) + beta -----
// Block: 64 pairs staged in smem; 4-thread team per pair; f32x2 accumulation.
__global__ void __launch_bounds__(256) pair_bias_kernel(
    const float* __restrict__ pair, const float* __restrict__ beta)
{
    __shared__ __align__(16) float xs[64][132];   // padded rows (528B, 16B-aligned)
    __shared__ __align__(16) float wsf[128*20];   // wgp rows padded to 20 floats
    __shared__ float csm[2*NH];
    int t = threadIdx.x;
    int q = blockIdx.y, k0 = blockIdx.x << 6;

    // stage wgp + consts
    for (int i=t; i<CPD*NH; i+=256) wsf[(i>>4)*20 + (i&15)] = g_wgp[i];
    if (t < 2*NH) csm[t] = g_cc[t];
    // stage 64 pair rows, coalesced float4
#pragma unroll
    for (int it=0; it<8; it++) {
        int i = t + (it<<8);
        int row = i >> 5, c4 = i & 31;
        *(float4*)&xs[row][c4<<2] =
            *(const float4*)(pair + (((size_t)((q<<10) + k0 + row))<<7) + (c4<<2));
    }
    __syncthreads();

    int p = t >> 2, c = t & 3;
    float sm = 0.f, sq = 0.f;
    ull acc2[8];
#pragma unroll
    for (int m=0;m<8;m++) acc2[m]=0ull;

    const float* xrow = &xs[p][0];
#pragma unroll
    for (int i=0;i<32;i++){
        int j = c + (i<<2);
        float xv = xrow[j];
        sm += xv; sq = fmaf(xv, xv, sq);
        ull xx = pk2(xv, xv);
        const float* wr = wsf + j*20;
        float4 w0 = *(const float4*)(wr);
        float4 w1 = *(const float4*)(wr+4);
        float4 w2 = *(const float4*)(wr+8);
        float4 w3 = *(const float4*)(wr+12);
        fma2(acc2[0], xx, pk2(w0.x,w0.y)); fma2(acc2[1], xx, pk2(w0.z,w0.w));
        fma2(acc2[2], xx, pk2(w1.x,w1.y)); fma2(acc2[3], xx, pk2(w1.z,w1.w));
        fma2(acc2[4], xx, pk2(w2.x,w2.y)); fma2(acc2[5], xx, pk2(w2.z,w2.w));
        fma2(acc2[6], xx, pk2(w3.x,w3.y)); fma2(acc2[7], xx, pk2(w3.z,w3.w));
    }
    // team reduce (lanes xor 1, 2)
#pragma unroll
    for (int o=1;o<4;o<<=1){
        sm += __shfl_xor_sync(0xffffffffu, sm, o);
        sq += __shfl_xor_sync(0xffffffffu, sq, o);
#pragma unroll
        for (int m=0;m<8;m++){
            ull v = __shfl_xor_sync(0xffffffffu, acc2[m], o);
            acc2[m] = add2(acc2[m], v);
        }
    }
    if (c == 0) {
        float mu = sm*(1.f/128.f);
        float rs = rsqrtf(sq*(1.f/128.f) - mu*mu + 1e-5f);
        int kk = k0 + p;
        float bv = beta[((size_t)q<<10) + kk];
        float murs = mu*rs;
#pragma unroll
        for (int m=0;m<8;m++){
            float2 v = up2(acc2[m]);
            int h0 = m<<1;
            float z0 = rs*v.x - murs*csm[NH+h0]   + csm[h0]   + bv;
            float z1 = rs*v.y - murs*csm[NH+h0+1] + csm[h0+1] + bv;
            g_bias[((size_t)h0<<20)     + ((size_t)q<<10) + kk] = z0;
            g_bias[((size_t)(h0+1)<<20) + ((size_t)q<<10) + kk] = z1;
        }
    }
}

// ---------------- flash attention: o[q, h*48+d] -----------------------------
// q/k/v come from packed qkvg buffer with row stride 3072.
__global__ void __launch_bounds__(128) attn_kernel(
    const float* __restrict__ qp, const float* __restrict__ kp,
    const float* __restrict__ vp)
{
    __shared__ __align__(16) float pool[6144];
    __shared__ float Ms[64], Ls[64];
    int t = threadIdx.x;
    int half = t>>6, ql = t&63;
    int h = blockIdx.y;
    int qr = (blockIdx.x<<6) + ql;
    float qv[48];
#pragma unroll
    for (int d=0; d<48; d++) qv[d] = qp[(size_t)qr*3072 + h*48 + d]*0.14433756729740643f;
    float m = -1e30f, l = 0.f, acc[48];
#pragma unroll
    for (int d=0; d<48; d++) acc[d]=0.f;
    int kb = half<<9;
    const float* brow = g_bias + ((size_t)h<<20) + ((size_t)qr<<10) + kb;
    for (int kt=0; kt<512; kt+=32) {
        __syncthreads();
#pragma unroll
        for (int it=0; it<6; it++) {
            int i4 = t + (it<<7);
            int d4 = i4 % 12;
            int rem = i4 / 12;
            int j = rem & 31, hh = rem >> 5;
            int krow = (hh<<9) + kt + j;
            ((float4*)pool)[i4]      = *(const float4*)(kp + (size_t)krow*3072 + h*48 + (d4<<2));
            ((float4*)pool)[768+i4]  = *(const float4*)(vp + (size_t)krow*3072 + h*48 + (d4<<2));
        }
        __syncthreads();
        float bb[32];
#pragma unroll
        for (int i=0;i<8;i++){
            float4 b4 = *(const float4*)(brow + kt + (i<<2));
            bb[i*4]=b4.x; bb[i*4+1]=b4.y; bb[i*4+2]=b4.z; bb[i*4+3]=b4.w;
        }
        const float* Kt = pool + half*1536;
        const float* Vt = pool + 3072 + half*1536;
        for (int j=0; j<32; j++) {
            const float4* kr4 = (const float4*)(Kt + j*48);
            float sd = 0.f;
#pragma unroll
            for (int d4=0; d4<12; d4++){
                float4 kk4 = kr4[d4];
                sd += qv[d4*4]*kk4.x + qv[d4*4+1]*kk4.y + qv[d4*4+2]*kk4.z + qv[d4*4+3]*kk4.w;
            }
            float sc = sd + bb[j];
            if (sc > m) {
                float corr = __expf(m - sc);
                l *= corr;
#pragma unroll
                for (int d=0; d<48; d++) acc[d] *= corr;
                m = sc;
            }
            float pw = __expf(sc - m);
            l += pw;
            const float4* vr4 = (const float4*)(Vt + j*48);
#pragma unroll
            for (int d4=0; d4<12; d4++){
                float4 vv4 = vr4[d4];
                acc[d4*4]   += pw*vv4.x; acc[d4*4+1] += pw*vv4.y;
                acc[d4*4+2] += pw*vv4.z; acc[d4*4+3] += pw*vv4.w;
            }
        }
    }
    __syncthreads();
    if (half == 1) {
        Ms[ql]=m; Ls[ql]=l;
#pragma unroll
        for (int d=0; d<48; d++) pool[ql*48+d]=acc[d];
    }
    __syncthreads();
    if (half == 0) {
        float m2=Ms[ql], l2=Ls[ql];
        float mn=fmaxf(m,m2);
        float c1=__expf(m-mn), c2=__expf(m2-mn);
        float inv=1.f/(l*c1 + l2*c2);
#pragma unroll
        for (int d=0; d<48; d++)
            g_o[(size_t)qr*CD + h*48 + d] = (acc[d]*c1 + pool[ql*48+d]*c2)*inv;
    }
}

// ---------------- small elementwise kernels ---------------------------------
__global__ void gate_mul_kernel() {
    int i = blockIdx.x*256 + threadIdx.x;
    int r = i / CD, c = i - r*CD;
    g_o[i] *= sigm(g_qkvg[(size_t)r*3072 + 2304 + c]);
}
__global__ void bout_kernel(const float* __restrict__ bso) {
    int i = blockIdx.x*256 + threadIdx.x;
    int r = i / CD, c = i - r*CD;
    g_bout[i] = sigm(g_ts2[(size_t)r*1536 + c] + bso[c])*g_attout[i];
}
__global__ void swiglu_kernel() {
    int i = blockIdx.x*256 + threadIdx.x;   // < NT*HD
    int r = i / HD, c = i - r*HD;
    float x = g_h12[(size_t)r*3072 + c];
    float y = g_h12[(size_t)r*3072 + 1536 + c];
    g_h1[i] = x*sigm(x)*y;
}
__global__ void final_kernel(const float* __restrict__ bs2, float* __restrict__ outp) {
    int i = blockIdx.x*256 + threadIdx.x;
    int r = i / CD, c = i - r*CD;
    outp[i] = g_bout[i] + sigm(g_ts2[(size_t)r*1536 + 768 + c] + bs2[c])*g_t3[i];
}

// ---------------- launch ----------------------------------------------------
extern "C" void kernel_launch(void* const* d_in, const int* in_sizes, int n_in,
                              void* d_out, int out_size)
{
    (void)in_sizes; (void)n_in; (void)out_size;
    const float* a     = (const float*)d_in[0];
    const float* s     = (const float*)d_in[1];
    const float* pair  = (const float*)d_in[2];
    const float* beta  = (const float*)d_in[3];
    const float* sg1   = (const float*)d_in[4];
    const float* wg1   = (const float*)d_in[5];
    const float* bg1   = (const float*)d_in[6];
    const float* wsk1  = (const float*)d_in[7];
    const float* wq    = (const float*)d_in[8];
    const float* bq    = (const float*)d_in[9];
    const float* wk    = (const float*)d_in[10];
    const float* wv    = (const float*)d_in[11];
    const float* gp    = (const float*)d_in[12];
    const float* bp    = (const float*)d_in[13];
    const float* wp    = (const float*)d_in[14];
    const float* wgate = (const float*)d_in[15];
    const float* wo    = (const float*)d_in[16];
    const float* wso   = (const float*)d_in[17];
    const float* bso   = (const float*)d_in[18];
    const float* sg2   = (const float*)d_in[19];
    const float* wg2   = (const float*)d_in[20];
    const float* bg2   = (const float*)d_in[21];
    const float* wsk2  = (const float*)d_in[22];
    const float* w1    = (const float*)d_in[23];
    const float* w2    = (const float*)d_in[24];
    const float* w3    = (const float*)d_in[25];
    const float* ws2   = (const float*)d_in[26];
    const float* bs2   = (const float*)d_in[27];

    float *p_sn1,*p_sn2,*p_an,*p_o,*p_attout,*p_h1,*p_t3,*p_tgk,*p_qkvg,*p_ts2,*p_h12;
    float *p_pk1,*p_pk2,*p_wqkvg,*p_wss,*p_w12,*p_bqkv;
    cudaGetSymbolAddress((void**)&p_sn1,   g_sn1);
    cudaGetSymbolAddress((void**)&p_sn2,   g_sn2);
    cudaGetSymbolAddress((void**)&p_an,    g_an);
    cudaGetSymbolAddress((void**)&p_o,     g_o);
    cudaGetSymbolAddress((void**)&p_attout,g_attout);
    cudaGetSymbolAddress((void**)&p_h1,    g_h1);
    cudaGetSymbolAddress((void**)&p_t3,    g_t3);
    cudaGetSymbolAddress((void**)&p_tgk,   g_tgk);
    cudaGetSymbolAddress((void**)&p_qkvg,  g_qkvg);
    cudaGetSymbolAddress((void**)&p_ts2,   g_ts2);
    cudaGetSymbolAddress((void**)&p_h12,   g_h12);
    cudaGetSymbolAddress((void**)&p_pk1,   g_pk1);
    cudaGetSymbolAddress((void**)&p_pk2,   g_pk2);
    cudaGetSymbolAddress((void**)&p_wqkvg, g_wqkvg);
    cudaGetSymbolAddress((void**)&p_wss,   g_wss);
    cudaGetSymbolAddress((void**)&p_w12,   g_w12);
    cudaGetSymbolAddress((void**)&p_bqkv,  g_bqkv);

    // ---- prep: LN, pair constants, weight packing ----
    ln_kernel<<<NT, 256>>>(a, s, sg1, sg2);
    pair_prep_kernel<<<1, 128>>>(gp, bp, wp);
    pack_kernel<<<576, 256>>>(wg1,   p_pk1,   192, 1536, 0);
    pack_kernel<<<576, 256>>>(wsk1,  p_pk1,   192, 1536, 768);
    pack_kernel<<<576, 256>>>(wq,    p_wqkvg, 192, 3072, 0);
    pack_kernel<<<576, 256>>>(wk,    p_wqkvg, 192, 3072, 768);
    pack_kernel<<<576, 256>>>(wv,    p_wqkvg, 192, 3072, 1536);
    pack_kernel<<<576, 256>>>(wgate, p_wqkvg, 192, 3072, 2304);
    pack_kernel<<<576, 256>>>(wso,   p_wss,   192, 1536, 0);
    pack_kernel<<<576, 256>>>(ws2,   p_wss,   192, 1536, 768);
    pack_kernel<<<576, 256>>>(wg2,   p_pk2,   192, 1536, 0);
    pack_kernel<<<576, 256>>>(wsk2,  p_pk2,   192, 1536, 768);
    pack_kernel<<<1152,256>>>(w1,    p_w12,   384, 3072, 0);
    pack_kernel<<<1152,256>>>(w2,    p_w12,   384, 3072, 1536);
    bfill_kernel<<<12, 256>>>(bq);

    // ---- pair bias (independent long pole, kick off early) ----
    pair_bias_kernel<<<dim3(16, 1024), 256>>>(pair, beta);

    // ---- AttentionPairBias ----
    sgemm64_kernel<<<dim3(24,16), 64>>>(p_sn1, p_pk1, nullptr, p_tgk, 1536, 768);
    adaln_combine_kernel<<<NT*CD/256, 256>>>(p_tgk, bg1, p_an);
    sgemm64_kernel<<<dim3(48,16), 64>>>(p_an, p_wqkvg, p_bqkv, p_qkvg, 3072, 768);
    attn_kernel<<<dim3(16, 16), 128>>>(p_qkvg, p_qkvg + 768, p_qkvg + 1536);
    gate_mul_kernel<<<NT*CD/256, 256>>>();
    sgemm64_kernel<<<dim3(12,16), 64>>>(p_o, wo, nullptr, p_attout, 768, 768);
    sgemm64_kernel<<<dim3(24,16), 64>>>(s, p_wss, nullptr, p_ts2, 1536, 768);
    bout_kernel<<<NT*CD/256, 256>>>(bso);

    // ---- ConditionedTransitionBlock ----
    sgemm64_kernel<<<dim3(24,16), 64>>>(p_sn2, p_pk2, nullptr, p_tgk, 1536, 768);
    adaln_combine_kernel<<<NT*CD/256, 256>>>(p_tgk, bg2, p_an);
    sgemm64_kernel<<<dim3(48,16), 64>>>(p_an, p_w12, nullptr, p_h12, 3072, 768);
    swiglu_kernel<<<NT*HD/256, 256>>>();
    sgemm64_kernel<<<dim3(12,16), 64>>>(p_h1, w3, nullptr, p_t3, 768, 1536);
    final_kernel<<<NT*CD/256, 256>>>(bs2, (float*)d_out);
}

// round 6
// speedup vs baseline: 1.6134x; 1.1224x over previous
#include <cuda_runtime.h>
#include <math.h>

#define NT 1024
#define CD 768
#define NH 16
#define DH 48
#define HD 1536
#define CPD 128

typedef unsigned long long ull;

// ---------------- f32x2 packed-math helpers (sm_100+) -----------------------
__device__ __forceinline__ ull pk2(float lo, float hi) {
    ull r; asm("mov.b64 %0, {%1, %2};" : "=l"(r) : "f"(lo), "f"(hi)); return r;
}
__device__ __forceinline__ void fma2(ull &d, ull a, ull b) {
    asm("fma.rn.f32x2 %0, %1, %2, %0;" : "+l"(d) : "l"(a), "l"(b));
}
__device__ __forceinline__ ull add2(ull a, ull b) {
    ull r; asm("add.rn.f32x2 %0, %1, %2;" : "=l"(r) : "l"(a), "l"(b)); return r;
}
__device__ __forceinline__ ull mul2(ull a, ull b) {
    ull r; asm("mul.rn.f32x2 %0, %1, %2;" : "=l"(r) : "l"(a), "l"(b)); return r;
}
__device__ __forceinline__ float2 up2(ull v) {
    float2 r; asm("mov.b64 {%0, %1}, %2;" : "=f"(r.x), "=f"(r.y) : "l"(v)); return r;
}
__device__ __forceinline__ float sigm(float x) { return 1.f/(1.f+__expf(-x)); }

// ---------------- scratch (device globals; no allocations allowed) ----------
__device__ __align__(16) float g_lna[NT*CD];
__device__ __align__(16) float g_sn1[NT*CD];
__device__ __align__(16) float g_sn2[NT*CD];
__device__ __align__(16) float g_an[NT*CD];
__device__ __align__(16) float g_o[NT*CD];
__device__ __align__(16) float g_attout[2*NT*CD];    // split-K partials
__device__ __align__(16) float g_bout[NT*CD];
__device__ __align__(16) float g_h1[NT*HD];
__device__ __align__(16) float g_t3[2*NT*CD];        // split-K partials
__device__ __align__(16) float g_tgk[NT*2*CD];       // tg|tk packed, stride 1536
__device__ __align__(16) float g_qkvg[NT*4*CD];      // q|k|v|gate, stride 3072
__device__ __align__(16) float g_ts2[NT*2*CD];       // s@wso | s@ws2, stride 1536
__device__ __align__(16) float g_h12[NT*2*HD];       // h1|h2, stride 3072
__device__ __align__(16) float g_bqkv[4*CD];
__device__ __align__(16) float g_wgp[CPD*NH];
__device__ __align__(16) float g_cc[2*NH];
__device__ __align__(16) float g_bias[(size_t)NH*NT*NT];   // 64 MB [h][q][k]

// ---------------- LayerNorm of a and s; sn1 = LN(s)*sg1, sn2 = LN(s)*sg2 ----
__global__ void ln_kernel(const float* __restrict__ a, const float* __restrict__ s,
                          const float* __restrict__ sg1, const float* __restrict__ sg2)
{
    int r = blockIdx.x, t = threadIdx.x;
    const float* ar = a + (size_t)r*CD;
    const float* sr = s + (size_t)r*CD;
    float va[3], vs[3];
    float s0=0.f,s1=0.f,s2=0.f,s3=0.f;
#pragma unroll
    for (int i=0;i<3;i++){
        va[i]=ar[t+256*i]; vs[i]=sr[t+256*i];
        s0+=va[i]; s1+=va[i]*va[i]; s2+=vs[i]; s3+=vs[i]*vs[i];
    }
    __shared__ float red[4][8];
    int lane=t&31, w=t>>5;
#pragma unroll
    for (int o=16;o;o>>=1){
        s0+=__shfl_xor_sync(0xffffffffu,s0,o);
        s1+=__shfl_xor_sync(0xffffffffu,s1,o);
        s2+=__shfl_xor_sync(0xffffffffu,s2,o);
        s3+=__shfl_xor_sync(0xffffffffu,s3,o);
    }
    if (lane==0){ red[0][w]=s0; red[1][w]=s1; red[2][w]=s2; red[3][w]=s3; }
    __syncthreads();
    float S0=0.f,S1=0.f,S2=0.f,S3=0.f;
#pragma unroll
    for (int i=0;i<8;i++){ S0+=red[0][i]; S1+=red[1][i]; S2+=red[2][i]; S3+=red[3][i]; }
    float mua=S0*(1.f/768.f), rsa=rsqrtf(S1*(1.f/768.f)-mua*mua+1e-5f);
    float mus=S2*(1.f/768.f), rss=rsqrtf(S3*(1.f/768.f)-mus*mus+1e-5f);
#pragma unroll
    for (int i=0;i<3;i++){
        int c=t+256*i; size_t idx=(size_t)r*CD+c;
        g_lna[idx]=(va[i]-mua)*rsa;
        float sv=(vs[i]-mus)*rss;
        g_sn1[idx]=sv*sg1[c];
        g_sn2[idx]=sv*sg2[c];
    }
}

__global__ void bfill_kernel(const float* __restrict__ bq)
{
    int i = blockIdx.x*256 + threadIdx.x;
    g_bqkv[i] = (i < CD) ? bq[i] : 0.f;
}

// ---------------- SGEMM: 64x64 tile, 64 threads, 8x8/thread, f32x2 ----------
// Multi-source B: column block cb maps to one of up to 4 source matrices of
// width bN each. Split-K via blockIdx.z: A offset z*K (lda = full row stride),
// B offset z*K rows, C offset z*cz.
__global__ void __launch_bounds__(64) sgemm64_kernel(
    const float* __restrict__ A, int lda,
    const float* __restrict__ B0, const float* __restrict__ B1,
    const float* __restrict__ B2, const float* __restrict__ B3,
    int bN, const float* __restrict__ biasv,
    float* __restrict__ C, int Nn, int K, int cz)
{
    __shared__ __align__(16) float As[2][8][64];
    __shared__ __align__(16) float Bs[2][8][64];
    int t = threadIdx.x;
    int z = blockIdx.z;
    int tx = t & 7, ty = t >> 3;
    int row0 = blockIdx.y << 6;
    int cb = blockIdx.x;
    int perSrc = bN >> 6;
    int si = cb / perSrc;
    const float* Bsel = (si==0) ? B0 : (si==1) ? B1 : (si==2) ? B2 : B3;
    int colSrc = (cb - si*perSrc) << 6;

    const float* Ag = A + (size_t)(row0 + t)*lda + (size_t)z*K;
    const float* Bg = Bsel + (size_t)z*K*bN + (size_t)(t>>3)*bN + colSrc + ((t&7)<<2);
    C += (size_t)z*cz;

    ull acc[8][4];
#pragma unroll
    for (int i=0;i<8;i++)
#pragma unroll
        for (int j=0;j<4;j++) acc[i][j]=0ull;

    int nt = K >> 3;
    float4 a0 = *(const float4*)(Ag);
    float4 a1 = *(const float4*)(Ag + 4);
    float4 b0 = *(const float4*)(Bg);
    float4 b1 = *(const float4*)(Bg + 32);
    {
        As[0][0][t]=a0.x; As[0][1][t]=a0.y; As[0][2][t]=a0.z; As[0][3][t]=a0.w;
        As[0][4][t]=a1.x; As[0][5][t]=a1.y; As[0][6][t]=a1.z; As[0][7][t]=a1.w;
        *(float4*)&Bs[0][t>>3][(t&7)<<2] = b0;
        *(float4*)&Bs[0][t>>3][((t&7)<<2)+32] = b1;
    }
    __syncthreads();

    for (int kt = 0; kt < nt; kt++) {
        int cur = kt & 1;
        bool more = (kt+1) < nt;
        if (more) {
            a0 = *(const float4*)(Ag + (kt+1)*8);
            a1 = *(const float4*)(Ag + (kt+1)*8 + 4);
            b0 = *(const float4*)(Bg + (size_t)(kt+1)*8*bN);
            b1 = *(const float4*)(Bg + (size_t)(kt+1)*8*bN + 32);
        }
#pragma unroll
        for (int kk = 0; kk < 8; kk++) {
            float4 av0 = *(const float4*)&As[cur][kk][ty<<3];
            float4 av1 = *(const float4*)&As[cur][kk][(ty<<3)+4];
            float4 bv0 = *(const float4*)&Bs[cur][kk][tx<<3];
            float4 bv1 = *(const float4*)&Bs[cur][kk][(tx<<3)+4];
            ull bp0 = pk2(bv0.x,bv0.y), bp1 = pk2(bv0.z,bv0.w);
            ull bp2 = pk2(bv1.x,bv1.y), bp3 = pk2(bv1.z,bv1.w);
            float aarr[8] = {av0.x,av0.y,av0.z,av0.w,av1.x,av1.y,av1.z,av1.w};
#pragma unroll
            for (int i=0;i<8;i++){
                ull aa = pk2(aarr[i], aarr[i]);
                fma2(acc[i][0], aa, bp0);
                fma2(acc[i][1], aa, bp1);
                fma2(acc[i][2], aa, bp2);
                fma2(acc[i][3], aa, bp3);
            }
        }
        if (more) {
            int nx = cur ^ 1;
            As[nx][0][t]=a0.x; As[nx][1][t]=a0.y; As[nx][2][t]=a0.z; As[nx][3][t]=a0.w;
            As[nx][4][t]=a1.x; As[nx][5][t]=a1.y; As[nx][6][t]=a1.z; As[nx][7][t]=a1.w;
            *(float4*)&Bs[nx][t>>3][(t&7)<<2] = b0;
            *(float4*)&Bs[nx][t>>3][((t&7)<<2)+32] = b1;
            __syncthreads();
        }
    }

    int col = (cb<<6) + (tx<<3);
    float4 bb0 = make_float4(0.f,0.f,0.f,0.f), bb1 = bb0;
    if (biasv) { bb0 = *(const float4*)(biasv + col); bb1 = *(const float4*)(biasv + col + 4); }
#pragma unroll
    for (int i=0;i<8;i++){
        int r = row0 + (ty<<3) + i;
        float2 p0=up2(acc[i][0]), p1=up2(acc[i][1]), p2=up2(acc[i][2]), p3=up2(acc[i][3]);
        float4 o0 = make_float4(p0.x+bb0.x, p0.y+bb0.y, p1.x+bb0.z, p1.y+bb0.w);
        float4 o1 = make_float4(p2.x+bb1.x, p2.y+bb1.y, p3.x+bb1.z, p3.y+bb1.w);
        *(float4*)(C + (size_t)r*Nn + col) = o0;
        *(float4*)(C + (size_t)r*Nn + col + 4) = o1;
    }
}

// ---------------- adaLN combine: an = sigmoid(tg+bg)*lna + tk ---------------
__global__ void adaln_combine_kernel(const float* __restrict__ tgk,
                                     const float* __restrict__ bgv,
                                     float* __restrict__ outp)
{
    int i = blockIdx.x*256 + threadIdx.x;
    int r = i / CD, c = i - r*CD;
    float tg = tgk[(size_t)r*1536 + c];
    float tk = tgk[(size_t)r*1536 + 768 + c];
    outp[i] = sigm(tg + bgv[c])*g_lna[i] + tk;
}

// ---------------- pair-bias precompute: wgp = gp*wp; c1,c2 ------------------
__global__ void pair_prep_kernel(const float* __restrict__ gp,
                                 const float* __restrict__ bp,
                                 const float* __restrict__ wp)
{
    int j = threadIdx.x;  // 128
    for (int h=0; h<NH; h++) g_wgp[j*NH+h] = gp[j]*wp[j*NH+h];
    __syncthreads();
    if (j < NH) {
        float c1=0.f, c2=0.f;
        for (int jj=0; jj<CPD; jj++){ c1 += bp[jj]*wp[jj*NH+j]; c2 += g_wgp[jj*NH+j]; }
        g_cc[j]=c1; g_cc[NH+j]=c2;
    }
}

// ---------------- pair bias: bias[h,q,k] = LN(pair)@wgp(+consts) + beta -----
__global__ void __launch_bounds__(256) pair_bias_kernel(
    const float* __restrict__ pair, const float* __restrict__ beta)
{
    __shared__ __align__(16) float xs[64][132];
    __shared__ __align__(16) float wsf[128*20];
    __shared__ float csm[2*NH];
    int t = threadIdx.x;
    int q = blockIdx.y, k0 = blockIdx.x << 6;

    for (int i=t; i<CPD*NH; i+=256) wsf[(i>>4)*20 + (i&15)] = g_wgp[i];
    if (t < 2*NH) csm[t] = g_cc[t];
#pragma unroll
    for (int it=0; it<8; it++) {
        int i = t + (it<<8);
        int row = i >> 5, c4 = i & 31;
        *(float4*)&xs[row][c4<<2] =
            *(const float4*)(pair + (((size_t)((q<<10) + k0 + row))<<7) + (c4<<2));
    }
    __syncthreads();

    int p = t >> 2, c = t & 3;
    float sm = 0.f, sq = 0.f;
    ull acc2[8];
#pragma unroll
    for (int m=0;m<8;m++) acc2[m]=0ull;

    const float* xrow = &xs[p][0];
#pragma unroll
    for (int i=0;i<32;i++){
        int j = c + (i<<2);
        float xv = xrow[j];
        sm += xv; sq = fmaf(xv, xv, sq);
        ull xx = pk2(xv, xv);
        const float* wr = wsf + j*20;
        float4 w0 = *(const float4*)(wr);
        float4 w1 = *(const float4*)(wr+4);
        float4 w2 = *(const float4*)(wr+8);
        float4 w3 = *(const float4*)(wr+12);
        fma2(acc2[0], xx, pk2(w0.x,w0.y)); fma2(acc2[1], xx, pk2(w0.z,w0.w));
        fma2(acc2[2], xx, pk2(w1.x,w1.y)); fma2(acc2[3], xx, pk2(w1.z,w1.w));
        fma2(acc2[4], xx, pk2(w2.x,w2.y)); fma2(acc2[5], xx, pk2(w2.z,w2.w));
        fma2(acc2[6], xx, pk2(w3.x,w3.y)); fma2(acc2[7], xx, pk2(w3.z,w3.w));
    }
#pragma unroll
    for (int o=1;o<4;o<<=1){
        sm += __shfl_xor_sync(0xffffffffu, sm, o);
        sq += __shfl_xor_sync(0xffffffffu, sq, o);
#pragma unroll
        for (int m=0;m<8;m++){
            ull v = __shfl_xor_sync(0xffffffffu, acc2[m], o);
            acc2[m] = add2(acc2[m], v);
        }
    }
    if (c == 0) {
        float mu = sm*(1.f/128.f);
        float rs = rsqrtf(sq*(1.f/128.f) - mu*mu + 1e-5f);
        int kk = k0 + p;
        float bv = beta[((size_t)q<<10) + kk];
        float murs = mu*rs;
#pragma unroll
        for (int m=0;m<8;m++){
            float2 v = up2(acc2[m]);
            int h0 = m<<1;
            float z0 = rs*v.x - murs*csm[NH+h0]   + csm[h0]   + bv;
            float z1 = rs*v.y - murs*csm[NH+h0+1] + csm[h0+1] + bv;
            g_bias[((size_t)h0<<20)     + ((size_t)q<<10) + kk] = z0;
            g_bias[((size_t)(h0+1)<<20) + ((size_t)q<<10) + kk] = z1;
        }
    }
}

// ---------------- flash attention (f32x2): o[q, h*48+d] ---------------------
__global__ void __launch_bounds__(128) attn_kernel(
    const float* __restrict__ qp, const float* __restrict__ kp,
    const float* __restrict__ vp)
{
    __shared__ __align__(16) float pool[6144];
    __shared__ float Ms[64], Ls[64];
    int t = threadIdx.x;
    int half = t>>6, ql = t&63;
    int h = blockIdx.y;
    int qr = (blockIdx.x<<6) + ql;
    const float scale = 0.14433756729740643f;
    ull q2[24];
#pragma unroll
    for (int d4=0; d4<12; d4++){
        float4 qq = *(const float4*)(qp + (size_t)qr*3072 + h*48 + (d4<<2));
        q2[d4*2]   = pk2(qq.x*scale, qq.y*scale);
        q2[d4*2+1] = pk2(qq.z*scale, qq.w*scale);
    }
    float m = -1e30f, l = 0.f;
    ull acc2[24];
#pragma unroll
    for (int i=0;i<24;i++) acc2[i]=0ull;
    int kb = half<<9;
    const float* brow = g_bias + ((size_t)h<<20) + ((size_t)qr<<10) + kb;
    for (int kt=0; kt<512; kt+=32) {
        __syncthreads();
#pragma unroll
        for (int it=0; it<6; it++) {
            int i4 = t + (it<<7);
            int d4 = i4 % 12;
            int rem = i4 / 12;
            int j = rem & 31, hh = rem >> 5;
            int krow = (hh<<9) + kt + j;
            ((float4*)pool)[i4]      = *(const float4*)(kp + (size_t)krow*3072 + h*48 + (d4<<2));
            ((float4*)pool)[768+i4]  = *(const float4*)(vp + (size_t)krow*3072 + h*48 + (d4<<2));
        }
        __syncthreads();
        float bb[32];
#pragma unroll
        for (int i=0;i<8;i++){
            float4 b4 = *(const float4*)(brow + kt + (i<<2));
            bb[i*4]=b4.x; bb[i*4+1]=b4.y; bb[i*4+2]=b4.z; bb[i*4+3]=b4.w;
        }
        const float* Kt = pool + half*1536;
        const float* Vt = pool + 3072 + half*1536;
        for (int j=0; j<32; j++) {
            const ull* kr2 = (const ull*)(Kt + j*48);
            ull d2 = 0ull;
#pragma unroll
            for (int i=0;i<24;i++) fma2(d2, q2[i], kr2[i]);
            float2 dd = up2(d2);
            float sc = dd.x + dd.y + bb[j];
            if (sc > m) {
                float corr = __expf(m - sc);
                l *= corr;
                ull cp = pk2(corr, corr);
#pragma unroll
                for (int i=0;i<24;i++) acc2[i] = mul2(acc2[i], cp);
                m = sc;
            }
            float pw = __expf(sc - m);
            l += pw;
            ull pp = pk2(pw, pw);
            const ull* vr2 = (const ull*)(Vt + j*48);
#pragma unroll
            for (int i=0;i<24;i++) fma2(acc2[i], pp, vr2[i]);
        }
    }
    __syncthreads();
    if (half == 1) {
        Ms[ql]=m; Ls[ql]=l;
#pragma unroll
        for (int i=0;i<24;i++){
            float2 v = up2(acc2[i]);
            pool[ql*48+2*i]=v.x; pool[ql*48+2*i+1]=v.y;
        }
    }
    __syncthreads();
    if (half == 0) {
        float m2=Ms[ql], l2=Ls[ql];
        float mn=fmaxf(m,m2);
        float c1=__expf(m-mn), c2=__expf(m2-mn);
        float inv=1.f/(l*c1 + l2*c2);
#pragma unroll
        for (int i=0;i<24;i++){
            float2 v = up2(acc2[i]);
            g_o[(size_t)qr*CD + h*48 + 2*i]   = (v.x*c1 + pool[ql*48+2*i]*c2)*inv;
            g_o[(size_t)qr*CD + h*48 + 2*i+1] = (v.y*c1 + pool[ql*48+2*i+1]*c2)*inv;
        }
    }
}

// ---------------- small elementwise kernels ---------------------------------
__global__ void gate_mul_kernel() {
    int i = blockIdx.x*256 + threadIdx.x;
    int r = i / CD, c = i - r*CD;
    g_o[i] *= sigm(g_qkvg[(size_t)r*3072 + 2304 + c]);
}
__global__ void bout_kernel(const float* __restrict__ bso) {
    int i = blockIdx.x*256 + threadIdx.x;
    int r = i / CD, c = i - r*CD;
    float att = g_attout[i] + g_attout[NT*CD + i];   // split-K sum
    g_bout[i] = sigm(g_ts2[(size_t)r*1536 + c] + bso[c])*att;
}
__global__ void swiglu_kernel() {
    int i = blockIdx.x*256 + threadIdx.x;   // < NT*HD
    int r = i / HD, c = i - r*HD;
    float x = g_h12[(size_t)r*3072 + c];
    float y = g_h12[(size_t)r*3072 + 1536 + c];
    g_h1[i] = x*sigm(x)*y;
}
__global__ void final_kernel(const float* __restrict__ bs2, float* __restrict__ outp) {
    int i = blockIdx.x*256 + threadIdx.x;
    int r = i / CD, c = i - r*CD;
    float t3 = g_t3[i] + g_t3[NT*CD + i];            // split-K sum
    outp[i] = g_bout[i] + sigm(g_ts2[(size_t)r*1536 + 768 + c] + bs2[c])*t3;
}

// ---------------- launch ----------------------------------------------------
extern "C" void kernel_launch(void* const* d_in, const int* in_sizes, int n_in,
                              void* d_out, int out_size)
{
    (void)in_sizes; (void)n_in; (void)out_size;
    const float* a     = (const float*)d_in[0];
    const float* s     = (const float*)d_in[1];
    const float* pair  = (const float*)d_in[2];
    const float* beta  = (const float*)d_in[3];
    const float* sg1   = (const float*)d_in[4];
    const float* wg1   = (const float*)d_in[5];
    const float* bg1   = (const float*)d_in[6];
    const float* wsk1  = (const float*)d_in[7];
    const float* wq    = (const float*)d_in[8];
    const float* bq    = (const float*)d_in[9];
    const float* wk    = (const float*)d_in[10];
    const float* wv    = (const float*)d_in[11];
    const float* gp    = (const float*)d_in[12];
    const float* bp    = (const float*)d_in[13];
    const float* wp    = (const float*)d_in[14];
    const float* wgate = (const float*)d_in[15];
    const float* wo    = (const float*)d_in[16];
    const float* wso   = (const float*)d_in[17];
    const float* bso   = (const float*)d_in[18];
    const float* sg2   = (const float*)d_in[19];
    const float* wg2   = (const float*)d_in[20];
    const float* bg2   = (const float*)d_in[21];
    const float* wsk2  = (const float*)d_in[22];
    const float* w1    = (const float*)d_in[23];
    const float* w2    = (const float*)d_in[24];
    const float* w3    = (const float*)d_in[25];
    const float* ws2   = (const float*)d_in[26];
    const float* bs2   = (const float*)d_in[27];

    float *p_sn1,*p_sn2,*p_an,*p_o,*p_attout,*p_h1,*p_t3,*p_tgk,*p_qkvg,*p_ts2,*p_h12,*p_bqkv;
    cudaGetSymbolAddress((void**)&p_sn1,   g_sn1);
    cudaGetSymbolAddress((void**)&p_sn2,   g_sn2);
    cudaGetSymbolAddress((void**)&p_an,    g_an);
    cudaGetSymbolAddress((void**)&p_o,     g_o);
    cudaGetSymbolAddress((void**)&p_attout,g_attout);
    cudaGetSymbolAddress((void**)&p_h1,    g_h1);
    cudaGetSymbolAddress((void**)&p_t3,    g_t3);
    cudaGetSymbolAddress((void**)&p_tgk,   g_tgk);
    cudaGetSymbolAddress((void**)&p_qkvg,  g_qkvg);
    cudaGetSymbolAddress((void**)&p_ts2,   g_ts2);
    cudaGetSymbolAddress((void**)&p_h12,   g_h12);
    cudaGetSymbolAddress((void**)&p_bqkv,  g_bqkv);

    // ---- prep ----
    ln_kernel<<<NT, 256>>>(a, s, sg1, sg2);
    pair_prep_kernel<<<1, 128>>>(gp, bp, wp);
    bfill_kernel<<<12, 256>>>(bq);

    // ---- pair bias (independent long pole) ----
    pair_bias_kernel<<<dim3(16, 1024), 256>>>(pair, beta);

    // ---- AttentionPairBias ----
    sgemm64_kernel<<<dim3(24,16,1), 64>>>(p_sn1, CD, wg1, wsk1, wg1, wg1, CD,
                                          nullptr, p_tgk, 1536, CD, 0);
    adaln_combine_kernel<<<NT*CD/256, 256>>>(p_tgk, bg1, p_an);
    sgemm64_kernel<<<dim3(48,16,1), 64>>>(p_an, CD, wq, wk, wv, wgate, CD,
                                          p_bqkv, p_qkvg, 3072, CD, 0);
    attn_kernel<<<dim3(16, 16), 128>>>(p_qkvg, p_qkvg + 768, p_qkvg + 1536);
    gate_mul_kernel<<<NT*CD/256, 256>>>();
    sgemm64_kernel<<<dim3(12,16,2), 64>>>(p_o, CD, wo, wo, wo, wo, CD,
                                          nullptr, p_attout, CD, 384, NT*CD);
    sgemm64_kernel<<<dim3(24,16,1), 64>>>(s, CD, wso, ws2, wso, wso, CD,
                                          nullptr, p_ts2, 1536, CD, 0);
    bout_kernel<<<NT*CD/256, 256>>>(bso);

    // ---- ConditionedTransitionBlock ----
    sgemm64_kernel<<<dim3(24,16,1), 64>>>(p_sn2, CD, wg2, wsk2, wg2, wg2, CD,
                                          nullptr, p_tgk, 1536, CD, 0);
    adaln_combine_kernel<<<NT*CD/256, 256>>>(p_tgk, bg2, p_an);
    sgemm64_kernel<<<dim3(48,16,1), 64>>>(p_an, CD, w1, w2, w1, w1, HD,
                                          nullptr, p_h12, 3072, CD, 0);
    swiglu_kernel<<<NT*HD/256, 256>>>();
    sgemm64_kernel<<<dim3(12,16,2), 64>>>(p_h1, HD, w3, w3, w3, w3, CD,
                                          nullptr, p_t3, CD, CD, NT*CD);
    final_kernel<<<NT*CD/256, 256>>>(bs2, (float*)d_out);
}